// round 16
// baseline (speedup 1.0000x reference)
#include <cuda_runtime.h>
#include <cuda_fp16.h>
#include <cstdint>

// Problem constants
#define D_IN   256
#define D_OUT  128
#define MAX_NODES 100000
#define MAX_EDGES 1600000

#define SCB 256                               // scan granularity
#define NB_SCAN ((MAX_NODES + SCB - 1) / SCB) // 391 scan blocks

// Static device scratch (no allocations anywhere)
__device__ __half g_support_h[(size_t)MAX_NODES * D_OUT]; // X@W+b (fp16)
__device__ int   g_cnt[MAX_NODES];                        // per-row degree
__device__ int   g_rowstart[MAX_NODES];                   // exclusive prefix
__device__ int   g_cur[MAX_NODES];                        // build cursor
__device__ int   g_partial[NB_SCAN];                      // scan block sums
__device__ int2  g_epack[MAX_EDGES];                      // CSR {col, val_bits}

// ---------------------------------------------------------------------------
// fp16 tensor-core GEMM (single MMA), double-buffered pipeline:
//   g_support_h[M,128] = fp16( A[M,256] @ W[256,128] + b )
// Block tile 128x128, K-step 16, ping/pong smem, ONE __syncthreads per iter.
// 256 threads = 8 warps (4m x 2n), warp tile 32x64, mma.m16n8k16.f16.
// ---------------------------------------------------------------------------
#define BM 128
#define BN 128
#define BK 16
#define NITER (D_IN / BK)
#define LDA 24            // As row stride (48B: conflict-free)
#define LDB 136           // Bs row stride (272B: conflict-free)

#define OFF_A 0
#define OFF_B 3072
#define BUF_ELEMS 5248

__device__ __forceinline__ void ldmatrix_x4(uint32_t* r, const void* p)
{
    uint32_t a = (uint32_t)__cvta_generic_to_shared(p);
    asm volatile("ldmatrix.sync.aligned.m8n8.x4.shared.b16 {%0,%1,%2,%3}, [%4];"
                 : "=r"(r[0]), "=r"(r[1]), "=r"(r[2]), "=r"(r[3]) : "r"(a));
}

__device__ __forceinline__ void ldmatrix_x4_trans(uint32_t* r, const void* p)
{
    uint32_t a = (uint32_t)__cvta_generic_to_shared(p);
    asm volatile("ldmatrix.sync.aligned.m8n8.x4.trans.shared.b16 {%0,%1,%2,%3}, [%4];"
                 : "=r"(r[0]), "=r"(r[1]), "=r"(r[2]), "=r"(r[3]) : "r"(a));
}

__device__ __forceinline__ void mma_f16(float* c, const uint32_t* a,
                                        uint32_t b0, uint32_t b1)
{
    asm volatile(
        "mma.sync.aligned.m16n8k16.row.col.f32.f16.f16.f32 "
        "{%0,%1,%2,%3}, {%4,%5,%6,%7}, {%8,%9}, {%0,%1,%2,%3};"
        : "+f"(c[0]), "+f"(c[1]), "+f"(c[2]), "+f"(c[3])
        : "r"(a[0]), "r"(a[1]), "r"(a[2]), "r"(a[3]), "r"(b0), "r"(b1));
}

__device__ __forceinline__ void cvt4(const float4& v, uint32_t* h)
{
    __half2 p0 = __floats2half2_rn(v.x, v.y);
    __half2 p1 = __floats2half2_rn(v.z, v.w);
    h[0] = *(uint32_t*)&p0;
    h[1] = *(uint32_t*)&p1;
}

__global__ __launch_bounds__(256) void gemm_bias_kernel(
    const float* __restrict__ A,
    const float* __restrict__ W,
    const float* __restrict__ b,
    int M)
{
    __shared__ __half smem_buf[2][BUF_ELEMS];

    const int tid  = threadIdx.x;
    const int lane = tid & 31;
    const int wid  = tid >> 5;
    const int wm   = (wid & 3) << 5;
    const int wn   = (wid >> 2) << 6;
    const int block_row = blockIdx.x * BM;

    const int a_row0 = tid >> 2;
    const int a_kq0  = (tid & 3) << 2;
    const int a_row1 = (tid + 256) >> 2;
    const int a_kq1  = ((tid + 256) & 3) << 2;
    const int b_kk0  = tid >> 5;
    const int b_n40  = (tid & 31) << 2;
    const int b_kk1  = (tid + 256) >> 5;
    const int b_n41  = ((tid + 256) & 31) << 2;

    const bool a_ok0 = (block_row + a_row0) < M;
    const bool a_ok1 = (block_row + a_row1) < M;
    const float* a_ptr0 = A + (size_t)(block_row + a_row0) * D_IN + a_kq0;
    const float* a_ptr1 = A + (size_t)(block_row + a_row1) * D_IN + a_kq1;
    const float* b_ptr0 = W + (size_t)b_kk0 * D_OUT + b_n40;
    const float* b_ptr1 = W + (size_t)b_kk1 * D_OUT + b_n41;

    float acc[2][8][4];
#pragma unroll
    for (int i = 0; i < 2; i++)
#pragma unroll
        for (int j = 0; j < 8; j++)
#pragma unroll
            for (int q = 0; q < 4; q++) acc[i][j][q] = 0.0f;

    float4 ra0, ra1, rb0, rb1;

    ra0 = a_ok0 ? *(const float4*)(a_ptr0) : make_float4(0.f,0.f,0.f,0.f);
    ra1 = a_ok1 ? *(const float4*)(a_ptr1) : make_float4(0.f,0.f,0.f,0.f);
    rb0 = *(const float4*)(b_ptr0);
    rb1 = *(const float4*)(b_ptr1);

    {
        __half* buf = smem_buf[0];
        uint32_t h[2];
        cvt4(ra0, h);
        ((uint32_t*)&buf[OFF_A + a_row0 * LDA + a_kq0])[0] = h[0];
        ((uint32_t*)&buf[OFF_A + a_row0 * LDA + a_kq0])[1] = h[1];
        cvt4(ra1, h);
        ((uint32_t*)&buf[OFF_A + a_row1 * LDA + a_kq1])[0] = h[0];
        ((uint32_t*)&buf[OFF_A + a_row1 * LDA + a_kq1])[1] = h[1];
        cvt4(rb0, h);
        ((uint32_t*)&buf[OFF_B + b_kk0 * LDB + b_n40])[0] = h[0];
        ((uint32_t*)&buf[OFF_B + b_kk0 * LDB + b_n40])[1] = h[1];
        cvt4(rb1, h);
        ((uint32_t*)&buf[OFF_B + b_kk1 * LDB + b_n41])[0] = h[0];
        ((uint32_t*)&buf[OFF_B + b_kk1 * LDB + b_n41])[1] = h[1];
    }
    __syncthreads();

#pragma unroll
    for (int it = 0; it < NITER; it++) {
        const int cur = it & 1;

        if (it + 1 < NITER) {
            const int k0 = (it + 1) * BK;
            ra0 = a_ok0 ? *(const float4*)(a_ptr0 + k0) : make_float4(0.f,0.f,0.f,0.f);
            ra1 = a_ok1 ? *(const float4*)(a_ptr1 + k0) : make_float4(0.f,0.f,0.f,0.f);
            rb0 = *(const float4*)(b_ptr0 + (size_t)k0 * D_OUT);
            rb1 = *(const float4*)(b_ptr1 + (size_t)k0 * D_OUT);
        }

        {
            const __half* buf = smem_buf[cur];
            uint32_t a[2][4];
#pragma unroll
            for (int im = 0; im < 2; im++) {
                const int mrow = wm + (im << 4) + (lane & 15);
                const int kcol = (lane >> 4) << 3;
                ldmatrix_x4(a[im], &buf[OFF_A + mrow * LDA + kcol]);
            }
#pragma unroll
            for (int jn2 = 0; jn2 < 4; jn2++) {
                const int krow = lane & 15;
                const int ncol = wn + (jn2 << 4) + ((lane >> 4) << 3);
                uint32_t bfr[4];
                ldmatrix_x4_trans(bfr, &buf[OFF_B + krow * LDB + ncol]);
#pragma unroll
                for (int im = 0; im < 2; im++) {
#pragma unroll
                    for (int j = 0; j < 2; j++) {
                        mma_f16(acc[im][(jn2 << 1) + j], a[im],
                                bfr[2 * j], bfr[2 * j + 1]);
                    }
                }
            }
        }

        if (it + 1 < NITER) {
            __half* buf = smem_buf[cur ^ 1];
            uint32_t h[2];
            cvt4(ra0, h);
            ((uint32_t*)&buf[OFF_A + a_row0 * LDA + a_kq0])[0] = h[0];
            ((uint32_t*)&buf[OFF_A + a_row0 * LDA + a_kq0])[1] = h[1];
            cvt4(ra1, h);
            ((uint32_t*)&buf[OFF_A + a_row1 * LDA + a_kq1])[0] = h[0];
            ((uint32_t*)&buf[OFF_A + a_row1 * LDA + a_kq1])[1] = h[1];
            cvt4(rb0, h);
            ((uint32_t*)&buf[OFF_B + b_kk0 * LDB + b_n40])[0] = h[0];
            ((uint32_t*)&buf[OFF_B + b_kk0 * LDB + b_n40])[1] = h[1];
            cvt4(rb1, h);
            ((uint32_t*)&buf[OFF_B + b_kk1 * LDB + b_n41])[0] = h[0];
            ((uint32_t*)&buf[OFF_B + b_kk1 * LDB + b_n41])[1] = h[1];
            __syncthreads();
        }
    }

    const int rq = lane >> 2;
    const int c2 = (lane & 3) << 1;
#pragma unroll
    for (int jn = 0; jn < 8; jn++) {
        const int col = wn + (jn << 3) + c2;
        const float b0 = b[col];
        const float b1 = b[col + 1];
#pragma unroll
        for (int im = 0; im < 2; im++) {
#pragma unroll
            for (int h = 0; h < 2; h++) {
                const int row = block_row + wm + (im << 4) + rq + (h << 3);
                if (row < M) {
                    __half2 v = __floats2half2_rn(acc[im][jn][2 * h + 0] + b0,
                                                  acc[im][jn][2 * h + 1] + b1);
                    *(__half2*)(g_support_h + (size_t)row * D_OUT + col) = v;
                }
            }
        }
    }
}

// ---------------------------------------------------------------------------
// CSR construction
// ---------------------------------------------------------------------------
__global__ __launch_bounds__(256) void zero_cnt_kernel(int M)
{
    int i = blockIdx.x * blockDim.x + threadIdx.x;
    if (i < M) g_cnt[i] = 0;
}

__global__ __launch_bounds__(256) void hist_kernel(
    const int* __restrict__ erow, int E)
{
    int i = blockIdx.x * blockDim.x + threadIdx.x;
    int stride = gridDim.x * blockDim.x;
    for (; i < E; i += stride)
        atomicAdd(&g_cnt[erow[i]], 1);
}

// Phase 1: per-256 block sums (391 blocks -> full-chip, short chains)
__global__ __launch_bounds__(SCB) void scan1_kernel(int M)
{
    __shared__ int ws[8];
    const int t    = threadIdx.x;
    const int lane = t & 31;
    const int wid  = t >> 5;
    const int i    = blockIdx.x * SCB + t;

    int x = (i < M) ? g_cnt[i] : 0;
#pragma unroll
    for (int off = 16; off > 0; off >>= 1)
        x += __shfl_down_sync(0xFFFFFFFFu, x, off);
    if (lane == 0) ws[wid] = x;
    __syncthreads();
    if (t == 0) {
        int s = 0;
#pragma unroll
        for (int w = 0; w < 8; w++) s += ws[w];
        g_partial[blockIdx.x] = s;
    }
}

// Phase 2 (fused): block-local exclusive scan + on-the-fly block offset.
__global__ __launch_bounds__(SCB) void scan3_kernel(int M, int nb)
{
    __shared__ int warp_sums[8];
    __shared__ int s_boff;

    const int t    = threadIdx.x;
    const int lane = t & 31;
    const int wid  = t >> 5;
    const int i    = blockIdx.x * SCB + t;

    int x = (i < M) ? g_cnt[i] : 0;

    // warp-inclusive scan
    int inc = x;
#pragma unroll
    for (int off = 1; off < 32; off <<= 1) {
        int n = __shfl_up_sync(0xFFFFFFFFu, inc, off);
        if (lane >= off) inc += n;
    }
    if (lane == 31) warp_sums[wid] = inc;

    // warp 1: block offset = sum g_partial[0 .. bid)
    if (wid == 1) {
        int a = 0;
        for (int j = lane; j < blockIdx.x; j += 32) a += g_partial[j];
#pragma unroll
        for (int off = 16; off > 0; off >>= 1)
            a += __shfl_down_sync(0xFFFFFFFFu, a, off);
        if (lane == 0) s_boff = a;
    }
    __syncthreads();

    // warp 0: exclusive scan of the 8 warp sums
    if (wid == 0) {
        int v = (lane < 8) ? warp_sums[lane] : 0;
        int orig = v;
#pragma unroll
        for (int off = 1; off < 8; off <<= 1) {
            int n = __shfl_up_sync(0xFFFFFFFFu, v, off);
            if (lane >= off) v += n;
        }
        if (lane < 8) warp_sums[lane] = v - orig;
    }
    __syncthreads();

    if (i < M) {
        int excl = s_boff + warp_sums[wid] + inc - x;
        g_rowstart[i] = excl;
        g_cur[i]      = excl;
    }
}

__global__ __launch_bounds__(256) void build_kernel(
    const int*   __restrict__ erow,
    const int*   __restrict__ ecol,
    const float* __restrict__ eval,
    int E)
{
    int i = blockIdx.x * blockDim.x + threadIdx.x;
    int stride = gridDim.x * blockDim.x;
    for (; i < E; i += stride) {
        int r = erow[i];
        int pos = atomicAdd(&g_cur[r], 1);
        g_epack[pos] = make_int2(ecol[i], __float_as_int(eval[i]));
    }
}

// ---------------------------------------------------------------------------
// Aggregation: one warp per row, 8x unrolled gathers (MLP=8), packed f32x2
// FMAs, cheap tanh. fp32 accumulate, fused store.
// ---------------------------------------------------------------------------
#define FMA2(accv, vv, mv) \
    asm("fma.rn.f32x2 %0, %1, %2, %0;" : "+l"(accv) : "l"(vv), "l"(mv))

__device__ __forceinline__ float fast_tanh(float x)
{
    float e = __expf(2.0f * x);
    return 1.0f - __fdividef(2.0f, e + 1.0f);
}

__device__ __forceinline__ void agg_edge(const int2 p, const uint2 u,
                                         unsigned long long& acc0,
                                         unsigned long long& acc1)
{
    const float v = __int_as_float(p.y);
    float2 f0 = __half22float2(*(__half2*)&u.x);
    float2 f1 = __half22float2(*(__half2*)&u.y);
    unsigned long long vv, m0, m1;
    asm("mov.b64 %0, {%1,%2};" : "=l"(vv) : "f"(v),    "f"(v));
    asm("mov.b64 %0, {%1,%2};" : "=l"(m0) : "f"(f0.x), "f"(f0.y));
    asm("mov.b64 %0, {%1,%2};" : "=l"(m1) : "f"(f1.x), "f"(f1.y));
    FMA2(acc0, vv, m0);
    FMA2(acc1, vv, m1);
}

__global__ __launch_bounds__(256) void row_agg_kernel(
    float* __restrict__ out, int M)
{
    const int row  = (int)((blockIdx.x * blockDim.x + threadIdx.x) >> 5);
    const int lane = threadIdx.x & 31;
    if (row >= M) return;

    const int start = g_rowstart[row];
    const int end   = start + g_cnt[row];
    const size_t loff = (size_t)(lane << 2);

    unsigned long long acc0, acc1;
    asm("mov.b64 %0, {%1,%2};" : "=l"(acc0) : "f"(0.0f), "f"(0.0f));
    acc1 = acc0;

    int e = start;
    for (; e + 7 < end; e += 8) {
        int2 p[8];
        uint2 u[8];
#pragma unroll
        for (int q = 0; q < 8; q++) p[q] = g_epack[e + q];
#pragma unroll
        for (int q = 0; q < 8; q++)
            u[q] = *(const uint2*)(g_support_h + (size_t)p[q].x * D_OUT + loff);
#pragma unroll
        for (int q = 0; q < 8; q++) agg_edge(p[q], u[q], acc0, acc1);
    }
    if (e + 3 < end) {
        int2 p[4];
        uint2 u[4];
#pragma unroll
        for (int q = 0; q < 4; q++) p[q] = g_epack[e + q];
#pragma unroll
        for (int q = 0; q < 4; q++)
            u[q] = *(const uint2*)(g_support_h + (size_t)p[q].x * D_OUT + loff);
#pragma unroll
        for (int q = 0; q < 4; q++) agg_edge(p[q], u[q], acc0, acc1);
        e += 4;
    }
    for (; e < end; e++) {
        int2 p = g_epack[e];
        uint2 u = *(const uint2*)(g_support_h + (size_t)p.x * D_OUT + loff);
        agg_edge(p, u, acc0, acc1);
    }

    float a0, a1, a2, a3;
    asm("mov.b64 {%0,%1}, %2;" : "=f"(a0), "=f"(a1) : "l"(acc0));
    asm("mov.b64 {%0,%1}, %2;" : "=f"(a2), "=f"(a3) : "l"(acc1));

    float4 r;
    r.x = fast_tanh(a0);
    r.y = fast_tanh(a1);
    r.z = fast_tanh(a2);
    r.w = fast_tanh(a3);
    *(float4*)(out + (size_t)row * D_OUT + loff) = r;
}

// ---------------------------------------------------------------------------
// Launch. Fork-join dual-stream: GEMM (independent) runs concurrently with
// the CSR chain; both join before row_agg. Stream/events created once and
// reused; all work is identical every call (graph-capturable, no allocs).
// inputs: 0=input [N,256] f32, 1=edge_row [E] i32, 2=edge_col [E] i32,
//         3=edge_val [E] f32, 4=W [256,128] f32, 5=b [128] f32
// ---------------------------------------------------------------------------
extern "C" void kernel_launch(void* const* d_in, const int* in_sizes, int n_in,
                              void* d_out, int out_size)
{
    const float* input    = (const float*)d_in[0];
    const int*   edge_row = (const int*)  d_in[1];
    const int*   edge_col = (const int*)  d_in[2];
    const float* edge_val = (const float*)d_in[3];
    const float* W        = (const float*)d_in[4];
    const float* b        = (const float*)d_in[5];
    float*       out      = (float*)d_out;

    const int M = in_sizes[0] / D_IN;   // 100000
    const int E = in_sizes[1];          // 1600000
    const int nb = (M + SCB - 1) / SCB; // 391

    static cudaStream_t s2 = nullptr;
    static cudaEvent_t ev_fork = nullptr, ev_join = nullptr;
    static int init_tried = 0;
    if (!init_tried) {
        init_tried = 1;
        if (cudaStreamCreateWithFlags(&s2, cudaStreamNonBlocking) != cudaSuccess) {
            s2 = nullptr;
        } else if (cudaEventCreateWithFlags(&ev_fork, cudaEventDisableTiming) != cudaSuccess ||
                   cudaEventCreateWithFlags(&ev_join, cudaEventDisableTiming) != cudaSuccess) {
            s2 = nullptr;
        }
    }

    if (s2) {
        // fork: GEMM on s2, concurrent with CSR chain on stream 0
        cudaEventRecord(ev_fork, 0);
        cudaStreamWaitEvent(s2, ev_fork, 0);
        gemm_bias_kernel<<<(M + BM - 1) / BM, 256, 0, s2>>>(input, W, b, M);
        cudaEventRecord(ev_join, s2);
    } else {
        gemm_bias_kernel<<<(M + BM - 1) / BM, 256, 0, 0>>>(input, W, b, M);
    }

    // CSR chain on stream 0
    zero_cnt_kernel<<<(M + 255) / 256, 256, 0, 0>>>(M);
    hist_kernel<<<1184, 256, 0, 0>>>(edge_row, E);
    scan1_kernel<<<nb, SCB, 0, 0>>>(M);
    scan3_kernel<<<nb, SCB, 0, 0>>>(M, nb);
    build_kernel<<<1184, 256, 0, 0>>>(edge_row, edge_col, edge_val, E);

    // join
    if (s2) cudaStreamWaitEvent(0, ev_join, 0);

    // Aggregate + tanh + store (warp per row)
    {
        const long long total_threads = (long long)M * 32;
        const int blocks = (int)((total_threads + 255) / 256);
        row_agg_kernel<<<blocks, 256, 0, 0>>>(out, M);
    }
}

// round 17
// speedup vs baseline: 1.5010x; 1.5010x over previous
#include <cuda_runtime.h>
#include <cuda_fp16.h>
#include <cstdint>

// Problem constants
#define D_IN   256
#define D_OUT  128
#define MAX_NODES 100000
#define MAX_EDGES 1600000

#define NB_SCAN ((MAX_NODES + 1023) / 1024)   // 98 scan blocks

// Static device scratch (no allocations anywhere)
__device__ __half g_support_h[(size_t)MAX_NODES * D_OUT]; // X@W+b (fp16)
__device__ int   g_cnt[MAX_NODES];                        // per-row degree
__device__ int   g_rowstart[MAX_NODES];                   // exclusive prefix
__device__ int   g_cur[MAX_NODES];                        // build cursor
__device__ int   g_partial[NB_SCAN];                      // scan block sums
__device__ int2  g_epack[MAX_EDGES];                      // CSR {col, val_bits}

// ---------------------------------------------------------------------------
// fp16 tensor-core GEMM device body (single MMA), double-buffered pipeline:
//   g_support_h[M,128] = fp16( A[M,256] @ W[256,128] + b )
// Block tile 128x128, K-step 16, ping/pong smem, ONE __syncthreads per iter.
// 256 threads = 8 warps (4m x 2n), warp tile 32x64, mma.m16n8k16.f16.
// Fused in one kernel with the edge-row histogram: blocks [0, gemm_blocks)
// run GEMM tiles, blocks [gemm_blocks, ..) run the histogram — tensor/smem
// work and L2-atomic work co-resident on the chip (intra-kernel overlap).
// ---------------------------------------------------------------------------
#define BM 128
#define BN 128
#define BK 16
#define NITER (D_IN / BK)
#define LDA 24            // As row stride (48B: conflict-free)
#define LDB 136           // Bs row stride (272B: conflict-free)

#define OFF_A 0
#define OFF_B 3072
#define BUF_ELEMS 5248    // 10496 B per buffer, x2 = 20992 B

__device__ __forceinline__ void ldmatrix_x4(uint32_t* r, const void* p)
{
    uint32_t a = (uint32_t)__cvta_generic_to_shared(p);
    asm volatile("ldmatrix.sync.aligned.m8n8.x4.shared.b16 {%0,%1,%2,%3}, [%4];"
                 : "=r"(r[0]), "=r"(r[1]), "=r"(r[2]), "=r"(r[3]) : "r"(a));
}

__device__ __forceinline__ void ldmatrix_x4_trans(uint32_t* r, const void* p)
{
    uint32_t a = (uint32_t)__cvta_generic_to_shared(p);
    asm volatile("ldmatrix.sync.aligned.m8n8.x4.trans.shared.b16 {%0,%1,%2,%3}, [%4];"
                 : "=r"(r[0]), "=r"(r[1]), "=r"(r[2]), "=r"(r[3]) : "r"(a));
}

__device__ __forceinline__ void mma_f16(float* c, const uint32_t* a,
                                        uint32_t b0, uint32_t b1)
{
    asm volatile(
        "mma.sync.aligned.m16n8k16.row.col.f32.f16.f16.f32 "
        "{%0,%1,%2,%3}, {%4,%5,%6,%7}, {%8,%9}, {%0,%1,%2,%3};"
        : "+f"(c[0]), "+f"(c[1]), "+f"(c[2]), "+f"(c[3])
        : "r"(a[0]), "r"(a[1]), "r"(a[2]), "r"(a[3]), "r"(b0), "r"(b1));
}

__device__ __forceinline__ void cvt4(const float4& v, uint32_t* h)
{
    __half2 p0 = __floats2half2_rn(v.x, v.y);
    __half2 p1 = __floats2half2_rn(v.z, v.w);
    h[0] = *(uint32_t*)&p0;
    h[1] = *(uint32_t*)&p1;
}

__device__ __forceinline__ void gemm_body(
    const float* __restrict__ A,
    const float* __restrict__ W,
    const float* __restrict__ b,
    int M, int gemm_bid, __half* smem_raw)
{
    __half (*smem_buf)[BUF_ELEMS] = (__half (*)[BUF_ELEMS])smem_raw;

    const int tid  = threadIdx.x;
    const int lane = tid & 31;
    const int wid  = tid >> 5;
    const int wm   = (wid & 3) << 5;
    const int wn   = (wid >> 2) << 6;
    const int block_row = gemm_bid * BM;

    const int a_row0 = tid >> 2;
    const int a_kq0  = (tid & 3) << 2;
    const int a_row1 = (tid + 256) >> 2;
    const int a_kq1  = ((tid + 256) & 3) << 2;
    const int b_kk0  = tid >> 5;
    const int b_n40  = (tid & 31) << 2;
    const int b_kk1  = (tid + 256) >> 5;
    const int b_n41  = ((tid + 256) & 31) << 2;

    const bool a_ok0 = (block_row + a_row0) < M;
    const bool a_ok1 = (block_row + a_row1) < M;
    const float* a_ptr0 = A + (size_t)(block_row + a_row0) * D_IN + a_kq0;
    const float* a_ptr1 = A + (size_t)(block_row + a_row1) * D_IN + a_kq1;
    const float* b_ptr0 = W + (size_t)b_kk0 * D_OUT + b_n40;
    const float* b_ptr1 = W + (size_t)b_kk1 * D_OUT + b_n41;

    float acc[2][8][4];
#pragma unroll
    for (int i = 0; i < 2; i++)
#pragma unroll
        for (int j = 0; j < 8; j++)
#pragma unroll
            for (int q = 0; q < 4; q++) acc[i][j][q] = 0.0f;

    float4 ra0, ra1, rb0, rb1;

    ra0 = a_ok0 ? *(const float4*)(a_ptr0) : make_float4(0.f,0.f,0.f,0.f);
    ra1 = a_ok1 ? *(const float4*)(a_ptr1) : make_float4(0.f,0.f,0.f,0.f);
    rb0 = *(const float4*)(b_ptr0);
    rb1 = *(const float4*)(b_ptr1);

    {
        __half* buf = smem_buf[0];
        uint32_t h[2];
        cvt4(ra0, h);
        ((uint32_t*)&buf[OFF_A + a_row0 * LDA + a_kq0])[0] = h[0];
        ((uint32_t*)&buf[OFF_A + a_row0 * LDA + a_kq0])[1] = h[1];
        cvt4(ra1, h);
        ((uint32_t*)&buf[OFF_A + a_row1 * LDA + a_kq1])[0] = h[0];
        ((uint32_t*)&buf[OFF_A + a_row1 * LDA + a_kq1])[1] = h[1];
        cvt4(rb0, h);
        ((uint32_t*)&buf[OFF_B + b_kk0 * LDB + b_n40])[0] = h[0];
        ((uint32_t*)&buf[OFF_B + b_kk0 * LDB + b_n40])[1] = h[1];
        cvt4(rb1, h);
        ((uint32_t*)&buf[OFF_B + b_kk1 * LDB + b_n41])[0] = h[0];
        ((uint32_t*)&buf[OFF_B + b_kk1 * LDB + b_n41])[1] = h[1];
    }
    __syncthreads();

#pragma unroll
    for (int it = 0; it < NITER; it++) {
        const int cur = it & 1;

        if (it + 1 < NITER) {
            const int k0 = (it + 1) * BK;
            ra0 = a_ok0 ? *(const float4*)(a_ptr0 + k0) : make_float4(0.f,0.f,0.f,0.f);
            ra1 = a_ok1 ? *(const float4*)(a_ptr1 + k0) : make_float4(0.f,0.f,0.f,0.f);
            rb0 = *(const float4*)(b_ptr0 + (size_t)k0 * D_OUT);
            rb1 = *(const float4*)(b_ptr1 + (size_t)k0 * D_OUT);
        }

        {
            const __half* buf = smem_buf[cur];
            uint32_t a[2][4];
#pragma unroll
            for (int im = 0; im < 2; im++) {
                const int mrow = wm + (im << 4) + (lane & 15);
                const int kcol = (lane >> 4) << 3;
                ldmatrix_x4(a[im], &buf[OFF_A + mrow * LDA + kcol]);
            }
#pragma unroll
            for (int jn2 = 0; jn2 < 4; jn2++) {
                const int krow = lane & 15;
                const int ncol = wn + (jn2 << 4) + ((lane >> 4) << 3);
                uint32_t bfr[4];
                ldmatrix_x4_trans(bfr, &buf[OFF_B + krow * LDB + ncol]);
#pragma unroll
                for (int im = 0; im < 2; im++) {
#pragma unroll
                    for (int j = 0; j < 2; j++) {
                        mma_f16(acc[im][(jn2 << 1) + j], a[im],
                                bfr[2 * j], bfr[2 * j + 1]);
                    }
                }
            }
        }

        if (it + 1 < NITER) {
            __half* buf = smem_buf[cur ^ 1];
            uint32_t h[2];
            cvt4(ra0, h);
            ((uint32_t*)&buf[OFF_A + a_row0 * LDA + a_kq0])[0] = h[0];
            ((uint32_t*)&buf[OFF_A + a_row0 * LDA + a_kq0])[1] = h[1];
            cvt4(ra1, h);
            ((uint32_t*)&buf[OFF_A + a_row1 * LDA + a_kq1])[0] = h[0];
            ((uint32_t*)&buf[OFF_A + a_row1 * LDA + a_kq1])[1] = h[1];
            cvt4(rb0, h);
            ((uint32_t*)&buf[OFF_B + b_kk0 * LDB + b_n40])[0] = h[0];
            ((uint32_t*)&buf[OFF_B + b_kk0 * LDB + b_n40])[1] = h[1];
            cvt4(rb1, h);
            ((uint32_t*)&buf[OFF_B + b_kk1 * LDB + b_n41])[0] = h[0];
            ((uint32_t*)&buf[OFF_B + b_kk1 * LDB + b_n41])[1] = h[1];
            __syncthreads();
        }
    }

    const int rq = lane >> 2;
    const int c2 = (lane & 3) << 1;
#pragma unroll
    for (int jn = 0; jn < 8; jn++) {
        const int col = wn + (jn << 3) + c2;
        const float b0 = b[col];
        const float b1 = b[col + 1];
#pragma unroll
        for (int im = 0; im < 2; im++) {
#pragma unroll
            for (int h = 0; h < 2; h++) {
                const int row = block_row + wm + (im << 4) + rq + (h << 3);
                if (row < M) {
                    __half2 v = __floats2half2_rn(acc[im][jn][2 * h + 0] + b0,
                                                  acc[im][jn][2 * h + 1] + b1);
                    *(__half2*)(g_support_h + (size_t)row * D_OUT + col) = v;
                }
            }
        }
    }
}

// Fused kernel: GEMM tiles + edge-row histogram, co-resident on the chip.
__global__ __launch_bounds__(256) void gemm_hist_kernel(
    const float* __restrict__ A,
    const float* __restrict__ W,
    const float* __restrict__ b,
    int M,
    const int* __restrict__ erow,
    int E,
    int gemm_blocks,
    int hist_blocks)
{
    __shared__ __half smem_raw[2 * BUF_ELEMS];

    if (blockIdx.x < (unsigned)gemm_blocks) {
        gemm_body(A, W, b, M, blockIdx.x, smem_raw);
    } else {
        const int hb = blockIdx.x - gemm_blocks;
        int i = hb * 256 + threadIdx.x;
        const int stride = hist_blocks * 256;
        for (; i < E; i += stride)
            atomicAdd(&g_cnt[erow[i]], 1);
    }
}

// ---------------------------------------------------------------------------
// CSR construction
// ---------------------------------------------------------------------------
__global__ __launch_bounds__(256) void zero_cnt_kernel(int M)
{
    int i = blockIdx.x * blockDim.x + threadIdx.x;
    if (i < M) g_cnt[i] = 0;
}

// Phase 1: per-block (1024 elems) sums
__global__ __launch_bounds__(1024) void scan1_kernel(int M)
{
    __shared__ int s[1024];
    const int t = threadIdx.x;
    const int i = blockIdx.x * 1024 + t;
    int x = (i < M) ? g_cnt[i] : 0;
    s[t] = x;
    __syncthreads();
#pragma unroll
    for (int off = 512; off > 0; off >>= 1) {
        if (t < off) s[t] += s[t + off];
        __syncthreads();
    }
    if (t == 0) g_partial[blockIdx.x] = s[0];
}

// Phase 2 (fused, shuffle-based): block-local exclusive scan + block offset.
__global__ __launch_bounds__(1024) void scan3_kernel(int M, int nb)
{
    __shared__ int warp_sums[32];
    __shared__ int s_boff;

    const int t    = threadIdx.x;
    const int lane = t & 31;
    const int wid  = t >> 5;
    const int i    = blockIdx.x * 1024 + t;

    int x = (i < M) ? g_cnt[i] : 0;

    int inc = x;
#pragma unroll
    for (int off = 1; off < 32; off <<= 1) {
        int n = __shfl_up_sync(0xFFFFFFFFu, inc, off);
        if (lane >= off) inc += n;
    }
    if (lane == 31) warp_sums[wid] = inc;

    if (wid == 1) {
        int a = 0;
        for (int j = lane; j < blockIdx.x; j += 32) a += g_partial[j];
#pragma unroll
        for (int off = 16; off > 0; off >>= 1)
            a += __shfl_down_sync(0xFFFFFFFFu, a, off);
        if (lane == 0) s_boff = a;
    }
    __syncthreads();

    if (wid == 0) {
        int ws = warp_sums[lane];
        int wsi = ws;
#pragma unroll
        for (int off = 1; off < 32; off <<= 1) {
            int n = __shfl_up_sync(0xFFFFFFFFu, wsi, off);
            if (lane >= off) wsi += n;
        }
        warp_sums[lane] = wsi - ws;
    }
    __syncthreads();

    if (i < M) {
        int excl = s_boff + warp_sums[wid] + inc - x;
        g_rowstart[i] = excl;
        g_cur[i]      = excl;
    }
}

__global__ __launch_bounds__(256) void build_kernel(
    const int*   __restrict__ erow,
    const int*   __restrict__ ecol,
    const float* __restrict__ eval,
    int E)
{
    int i = blockIdx.x * blockDim.x + threadIdx.x;
    int stride = gridDim.x * blockDim.x;
    for (; i < E; i += stride) {
        int r = erow[i];
        int pos = atomicAdd(&g_cur[r], 1);
        g_epack[pos] = make_int2(ecol[i], __float_as_int(eval[i]));
    }
}

// ---------------------------------------------------------------------------
// Aggregation: one warp per row, 8x unrolled gathers (MLP=8), packed f32x2
// FMAs, cheap tanh. fp32 accumulate, fused store.
// ---------------------------------------------------------------------------
#define FMA2(accv, vv, mv) \
    asm("fma.rn.f32x2 %0, %1, %2, %0;" : "+l"(accv) : "l"(vv), "l"(mv))

__device__ __forceinline__ float fast_tanh(float x)
{
    float e = __expf(2.0f * x);
    return 1.0f - __fdividef(2.0f, e + 1.0f);
}

__device__ __forceinline__ void agg_edge(const int2 p, const uint2 u,
                                         unsigned long long& acc0,
                                         unsigned long long& acc1)
{
    const float v = __int_as_float(p.y);
    float2 f0 = __half22float2(*(__half2*)&u.x);
    float2 f1 = __half22float2(*(__half2*)&u.y);
    unsigned long long vv, m0, m1;
    asm("mov.b64 %0, {%1,%2};" : "=l"(vv) : "f"(v),    "f"(v));
    asm("mov.b64 %0, {%1,%2};" : "=l"(m0) : "f"(f0.x), "f"(f0.y));
    asm("mov.b64 %0, {%1,%2};" : "=l"(m1) : "f"(f1.x), "f"(f1.y));
    FMA2(acc0, vv, m0);
    FMA2(acc1, vv, m1);
}

__global__ __launch_bounds__(256) void row_agg_kernel(
    float* __restrict__ out, int M)
{
    const int row  = (int)((blockIdx.x * blockDim.x + threadIdx.x) >> 5);
    const int lane = threadIdx.x & 31;
    if (row >= M) return;

    const int start = g_rowstart[row];
    const int end   = start + g_cnt[row];
    const size_t loff = (size_t)(lane << 2);

    unsigned long long acc0, acc1;
    asm("mov.b64 %0, {%1,%2};" : "=l"(acc0) : "f"(0.0f), "f"(0.0f));
    acc1 = acc0;

    int e = start;
    for (; e + 7 < end; e += 8) {
        int2 p[8];
        uint2 u[8];
#pragma unroll
        for (int q = 0; q < 8; q++) p[q] = g_epack[e + q];
#pragma unroll
        for (int q = 0; q < 8; q++)
            u[q] = *(const uint2*)(g_support_h + (size_t)p[q].x * D_OUT + loff);
#pragma unroll
        for (int q = 0; q < 8; q++) agg_edge(p[q], u[q], acc0, acc1);
    }
    if (e + 3 < end) {
        int2 p[4];
        uint2 u[4];
#pragma unroll
        for (int q = 0; q < 4; q++) p[q] = g_epack[e + q];
#pragma unroll
        for (int q = 0; q < 4; q++)
            u[q] = *(const uint2*)(g_support_h + (size_t)p[q].x * D_OUT + loff);
#pragma unroll
        for (int q = 0; q < 4; q++) agg_edge(p[q], u[q], acc0, acc1);
        e += 4;
    }
    for (; e < end; e++) {
        int2 p = g_epack[e];
        uint2 u = *(const uint2*)(g_support_h + (size_t)p.x * D_OUT + loff);
        agg_edge(p, u, acc0, acc1);
    }

    float a0, a1, a2, a3;
    asm("mov.b64 {%0,%1}, %2;" : "=f"(a0), "=f"(a1) : "l"(acc0));
    asm("mov.b64 {%0,%1}, %2;" : "=f"(a2), "=f"(a3) : "l"(acc1));

    float4 r;
    r.x = fast_tanh(a0);
    r.y = fast_tanh(a1);
    r.z = fast_tanh(a2);
    r.w = fast_tanh(a3);
    *(float4*)(out + (size_t)row * D_OUT + loff) = r;
}

// ---------------------------------------------------------------------------
// Launch. SINGLE stream (round-16 lesson: stream fork-join in the captured
// graph regressed). Overlap happens inside gemm_hist_kernel instead.
// inputs: 0=input [N,256] f32, 1=edge_row [E] i32, 2=edge_col [E] i32,
//         3=edge_val [E] f32, 4=W [256,128] f32, 5=b [128] f32
// ---------------------------------------------------------------------------
extern "C" void kernel_launch(void* const* d_in, const int* in_sizes, int n_in,
                              void* d_out, int out_size)
{
    const float* input    = (const float*)d_in[0];
    const int*   edge_row = (const int*)  d_in[1];
    const int*   edge_col = (const int*)  d_in[2];
    const float* edge_val = (const float*)d_in[3];
    const float* W        = (const float*)d_in[4];
    const float* b        = (const float*)d_in[5];
    float*       out      = (float*)d_out;

    const int M = in_sizes[0] / D_IN;   // 100000
    const int E = in_sizes[1];          // 1600000
    const int nb = (M + 1023) / 1024;   // 98

    const int gemm_blocks = (M + BM - 1) / BM;   // 782
    const int hist_blocks = 1184;

    // 1) zero counts
    zero_cnt_kernel<<<(M + 255) / 256, 256, 0, 0>>>(M);

    // 2) fused: GEMM (tensor pipe) + histogram (L2 atomics), co-resident
    gemm_hist_kernel<<<gemm_blocks + hist_blocks, 256, 0, 0>>>(
        input, W, b, M, edge_row, E, gemm_blocks, hist_blocks);

    // 3) scan
    scan1_kernel<<<nb, 1024, 0, 0>>>(M);
    scan3_kernel<<<nb, 1024, 0, 0>>>(M, nb);

    // 4) CSR permute
    build_kernel<<<1184, 256, 0, 0>>>(edge_row, edge_col, edge_val, E);

    // 5) aggregate + tanh + store (warp per row)
    {
        const long long total_threads = (long long)M * 32;
        const int blocks = (int)((total_threads + 255) / 256);
        row_agg_kernel<<<blocks, 256, 0, 0>>>(out, M);
    }
}